// round 1
// baseline (speedup 1.0000x reference)
#include <cuda_runtime.h>
#include <cuda_bf16.h>
#include <math.h>

// Problem constants (from reference): N = M = 8192, D = 256.
#define DDIM 256
#define MAXROWS 8192

// Scratch (allocation-free rule: __device__ globals)
__device__ float g_A[MAXROWS * DDIM];   // x1 * sqrt(alpha)
__device__ float g_B[MAXROWS * DDIM];   // x2 * sqrt(alpha)
__device__ float g_n1[MAXROWS];         // ||a_i||^2
__device__ float g_n2[MAXROWS];         // ||b_j||^2
__device__ float g_sa[DDIM];            // sqrt(alpha)
__device__ float g_var;                 // variance_raw^2

// ---------------------------------------------------------------------------
// Kernel 1: alpha = softmax(alpha_raw^2); store sqrt(alpha), variance.
// One block of 256 threads.
// ---------------------------------------------------------------------------
__global__ void prep_alpha_kernel(const float* __restrict__ alpha_raw,
                                  const float* __restrict__ variance_raw) {
    __shared__ float sh[DDIM];
    int d = threadIdx.x;
    float t = alpha_raw[d] * alpha_raw[d];

    // max reduce
    sh[d] = t;
    __syncthreads();
    #pragma unroll
    for (int s = 128; s > 0; s >>= 1) {
        if (d < s) sh[d] = fmaxf(sh[d], sh[d + s]);
        __syncthreads();
    }
    float mx = sh[0];
    __syncthreads();

    float e = expf(t - mx);
    sh[d] = e;
    __syncthreads();
    #pragma unroll
    for (int s = 128; s > 0; s >>= 1) {
        if (d < s) sh[d] += sh[d + s];
        __syncthreads();
    }
    float sum = sh[0];

    g_sa[d] = sqrtf(e / sum);
    if (d == 0) g_var = variance_raw[0] * variance_raw[0];
}

// ---------------------------------------------------------------------------
// Kernel 2: scale rows by sqrt(alpha), compute row norms.
// One block (256 threads) per row.
// ---------------------------------------------------------------------------
__global__ void scale_rows_kernel(const float* __restrict__ x,
                                  float* __restrict__ out,
                                  float* __restrict__ nrm) {
    __shared__ float sh[DDIM];
    int row = blockIdx.x;
    int d   = threadIdx.x;
    float v = x[(size_t)row * DDIM + d] * g_sa[d];
    out[(size_t)row * DDIM + d] = v;

    sh[d] = v * v;
    __syncthreads();
    #pragma unroll
    for (int s = 128; s > 0; s >>= 1) {
        if (d < s) sh[d] += sh[d + s];
        __syncthreads();
    }
    if (d == 0) nrm[row] = sh[0];
}

// ---------------------------------------------------------------------------
// Kernel 3: fused GEMM + RBF epilogue.
// Tile 128x128, BK=16, 256 threads, 8x8 per thread.
// out[i][j] = var * exp(-0.5 * max(n1[i] + n2[j] - 2*dot(a_i, b_j), 0))
// ---------------------------------------------------------------------------
#define BM 128
#define BN 128
#define BK 16

__global__ __launch_bounds__(256, 2)
void rbf_gemm_kernel(const float* __restrict__ A,
                     const float* __restrict__ B,
                     const float* __restrict__ n1,
                     const float* __restrict__ n2,
                     float* __restrict__ out,
                     int Mcols) {
    __shared__ float As[BK][BM + 4];
    __shared__ float Bs[BK][BN + 4];

    const int tid  = threadIdx.x;
    const int tx   = tid & 15;        // n direction (8 cols each)
    const int ty   = tid >> 4;        // m direction (8 rows each)
    const int row0 = blockIdx.y * BM;
    const int col0 = blockIdx.x * BN;

    float acc[8][8];
    #pragma unroll
    for (int i = 0; i < 8; i++)
        #pragma unroll
        for (int j = 0; j < 8; j++) acc[i][j] = 0.0f;

    for (int kk = 0; kk < DDIM; kk += BK) {
        // Load 128x16 tiles of A and B (transposed into smem).
        // 512 float4 loads per tile, 256 threads -> 2 each.
        #pragma unroll
        for (int l = 0; l < 2; l++) {
            int q = tid + l * 256;
            int r = q >> 2;           // row within tile [0,128)
            int c = q & 3;            // float4 index within BK [0,4)
            float4 va = *(const float4*)(A + (size_t)(row0 + r) * DDIM + kk + c * 4);
            As[c * 4 + 0][r] = va.x;
            As[c * 4 + 1][r] = va.y;
            As[c * 4 + 2][r] = va.z;
            As[c * 4 + 3][r] = va.w;
            float4 vb = *(const float4*)(B + (size_t)(col0 + r) * DDIM + kk + c * 4);
            Bs[c * 4 + 0][r] = vb.x;
            Bs[c * 4 + 1][r] = vb.y;
            Bs[c * 4 + 2][r] = vb.z;
            Bs[c * 4 + 3][r] = vb.w;
        }
        __syncthreads();

        #pragma unroll
        for (int k = 0; k < BK; k++) {
            float a[8], b[8];
            *(float4*)(a)     = *(const float4*)&As[k][ty * 8];
            *(float4*)(a + 4) = *(const float4*)&As[k][ty * 8 + 4];
            *(float4*)(b)     = *(const float4*)&Bs[k][tx * 8];
            *(float4*)(b + 4) = *(const float4*)&Bs[k][tx * 8 + 4];
            #pragma unroll
            for (int i = 0; i < 8; i++)
                #pragma unroll
                for (int j = 0; j < 8; j++)
                    acc[i][j] = fmaf(a[i], b[j], acc[i][j]);
        }
        __syncthreads();
    }

    // Epilogue
    const float var = g_var;
    float rn1[8], rn2[8];
    #pragma unroll
    for (int i = 0; i < 8; i++) rn1[i] = n1[row0 + ty * 8 + i];
    #pragma unroll
    for (int j = 0; j < 8; j++) rn2[j] = n2[col0 + tx * 8 + j];

    #pragma unroll
    for (int i = 0; i < 8; i++) {
        float v[8];
        #pragma unroll
        for (int j = 0; j < 8; j++) {
            float sq = fmaf(-2.0f, acc[i][j], rn1[i] + rn2[j]);
            sq = fmaxf(sq, 0.0f);
            v[j] = var * __expf(-0.5f * sq);
        }
        size_t o = (size_t)(row0 + ty * 8 + i) * (size_t)Mcols + (size_t)(col0 + tx * 8);
        *(float4*)(out + o)     = *(const float4*)(v);
        *(float4*)(out + o + 4) = *(const float4*)(v + 4);
    }
}

// ---------------------------------------------------------------------------
// Launch
// ---------------------------------------------------------------------------
extern "C" void kernel_launch(void* const* d_in, const int* in_sizes, int n_in,
                              void* d_out, int out_size) {
    const float* x1 = (const float*)d_in[0];
    const float* x2 = (const float*)d_in[1];
    const float* alpha_raw    = (const float*)d_in[2];
    const float* variance_raw = (const float*)d_in[3];
    float* out = (float*)d_out;

    int N = in_sizes[0] / DDIM;
    int M = in_sizes[1] / DDIM;

    float *A, *B, *n1, *n2;
    cudaGetSymbolAddress((void**)&A,  g_A);
    cudaGetSymbolAddress((void**)&B,  g_B);
    cudaGetSymbolAddress((void**)&n1, g_n1);
    cudaGetSymbolAddress((void**)&n2, g_n2);

    prep_alpha_kernel<<<1, DDIM>>>(alpha_raw, variance_raw);
    scale_rows_kernel<<<N, DDIM>>>(x1, A, n1);
    scale_rows_kernel<<<M, DDIM>>>(x2, B, n2);

    dim3 grid(M / BN, N / BM);
    rbf_gemm_kernel<<<grid, 256>>>(A, B, n1, n2, out, M);
}

// round 3
// speedup vs baseline: 2.6263x; 2.6263x over previous
#include <cuda_runtime.h>
#include <cuda_bf16.h>
#include <math.h>
#include <stdint.h>

#define DDIM 256
#define NROWS 8192
#define K2 512                 // A-side split K (hi || lo)
#define BM 128
#define BN 128
#define BK 32                  // bf16 per k-chunk
#define NITER (K2 / BK)        // 16
#define NSTAGE 4
#define ROWB 80                // smem bytes per row: 64 data + 16 pad
#define A_BYTES (BM * ROWB)    // 10240
#define STAGE_BYTES (2 * A_BYTES)
#define SMEM_TOTAL (NSTAGE * STAGE_BYTES)

// -------------------- scratch --------------------
__device__ __nv_bfloat16 g_A2[NROWS * K2];    // x1*sa: hi (k<256) | lo (k>=256)
__device__ __nv_bfloat16 g_Bh[NROWS * DDIM];  // x2*sa: hi only
__device__ float g_n1[NROWS];
__device__ float g_n2[NROWS];
__device__ float g_sa[DDIM];
__device__ float g_var;

// -------------------- helpers --------------------
__device__ __forceinline__ uint32_t smem_u32(const void* p) {
    uint32_t a;
    asm("{ .reg .u64 t; cvta.to.shared.u64 t, %1; cvt.u32.u64 %0, t; }" : "=r"(a) : "l"(p));
    return a;
}
__device__ __forceinline__ void cp_async16(uint32_t saddr, const void* g) {
    asm volatile("cp.async.cg.shared.global [%0], [%1], 16;" :: "r"(saddr), "l"(g));
}
__device__ __forceinline__ void ldmatrix_x4(uint32_t* r, uint32_t saddr) {
    asm volatile("ldmatrix.sync.aligned.m8n8.x4.shared.b16 {%0,%1,%2,%3}, [%4];"
                 : "=r"(r[0]), "=r"(r[1]), "=r"(r[2]), "=r"(r[3]) : "r"(saddr));
}
__device__ __forceinline__ void mma_bf16(float* c, const uint32_t* a, const uint32_t* b) {
    asm volatile(
        "mma.sync.aligned.m16n8k16.row.col.f32.bf16.bf16.f32 "
        "{%0,%1,%2,%3}, {%4,%5,%6,%7}, {%8,%9}, {%0,%1,%2,%3};"
        : "+f"(c[0]), "+f"(c[1]), "+f"(c[2]), "+f"(c[3])
        : "r"(a[0]), "r"(a[1]), "r"(a[2]), "r"(a[3]), "r"(b[0]), "r"(b[1]));
}

// -------------------- prep --------------------
__global__ void prep_alpha_kernel(const float* __restrict__ alpha_raw,
                                  const float* __restrict__ variance_raw) {
    __shared__ float sh[DDIM];
    int d = threadIdx.x;
    float t = alpha_raw[d] * alpha_raw[d];
    sh[d] = t;
    __syncthreads();
    #pragma unroll
    for (int s = 128; s > 0; s >>= 1) {
        if (d < s) sh[d] = fmaxf(sh[d], sh[d + s]);
        __syncthreads();
    }
    float mx = sh[0];
    __syncthreads();
    float e = expf(t - mx);
    sh[d] = e;
    __syncthreads();
    #pragma unroll
    for (int s = 128; s > 0; s >>= 1) {
        if (d < s) sh[d] += sh[d + s];
        __syncthreads();
    }
    g_sa[d] = sqrtf(e / sh[0]);
    if (d == 0) g_var = variance_raw[0] * variance_raw[0];
}

// split into hi+lo bf16 (K2 layout), plus exact fp32 row norm
__global__ void scale_split_kernel(const float* __restrict__ x,
                                   __nv_bfloat16* __restrict__ out,
                                   float* __restrict__ nrm) {
    __shared__ float sh[DDIM];
    int row = blockIdx.x, d = threadIdx.x;
    float v = x[(size_t)row * DDIM + d] * g_sa[d];
    __nv_bfloat16 hi = __float2bfloat16(v);
    out[(size_t)row * K2 + d] = hi;
    out[(size_t)row * K2 + DDIM + d] = __float2bfloat16(v - __bfloat162float(hi));
    sh[d] = v * v;
    __syncthreads();
    #pragma unroll
    for (int s = 128; s > 0; s >>= 1) {
        if (d < s) sh[d] += sh[d + s];
        __syncthreads();
    }
    if (d == 0) nrm[row] = sh[0];
}

// hi only
__global__ void scale_hi_kernel(const float* __restrict__ x,
                                __nv_bfloat16* __restrict__ out,
                                float* __restrict__ nrm) {
    __shared__ float sh[DDIM];
    int row = blockIdx.x, d = threadIdx.x;
    float v = x[(size_t)row * DDIM + d] * g_sa[d];
    out[(size_t)row * DDIM + d] = __float2bfloat16(v);
    sh[d] = v * v;
    __syncthreads();
    #pragma unroll
    for (int s = 128; s > 0; s >>= 1) {
        if (d < s) sh[d] += sh[d + s];
        __syncthreads();
    }
    if (d == 0) nrm[row] = sh[0];
}

// -------------------- fused HMMA GEMM + RBF epilogue --------------------
__global__ void __launch_bounds__(256, 1)
rbf_mma_kernel(const __nv_bfloat16* __restrict__ A2,
               const __nv_bfloat16* __restrict__ Bh,
               const float* __restrict__ n1,
               const float* __restrict__ n2,
               float* __restrict__ out,
               int Mcols) {
    extern __shared__ char smem[];
    const uint32_t sbase = smem_u32(smem);
    const int tid = threadIdx.x;
    const int wid = tid >> 5;
    const int lane = tid & 31;
    const int wm = wid & 3;       // 4 warps in M, 32 rows each
    const int wn = wid >> 2;      // 2 warps in N, 64 cols each
    const int row0 = blockIdx.y * BM;
    const int col0 = blockIdx.x * BN;

    float acc[2][8][4];
    #pragma unroll
    for (int i = 0; i < 2; i++)
        #pragma unroll
        for (int j = 0; j < 8; j++)
            #pragma unroll
            for (int q = 0; q < 4; q++) acc[i][j][q] = 0.0f;

    // fill one stage: A 128x32 bf16 + B 128x32 bf16, 1024 16B chunks / 256 thr
    auto fill = [&](int ck) {
        const int kk = ck * BK;
        const int kb = kk & (DDIM - 1);
        const uint32_t ab = sbase + (ck & (NSTAGE - 1)) * STAGE_BYTES;
        const uint32_t bb = ab + A_BYTES;
        #pragma unroll
        for (int l = 0; l < 2; l++) {
            int u = tid + l * 256;
            int r = u >> 2, c = u & 3;
            cp_async16(ab + (uint32_t)(r * ROWB + c * 16),
                       A2 + (size_t)(row0 + r) * K2 + kk + c * 8);
        }
        #pragma unroll
        for (int l = 0; l < 2; l++) {
            int u = tid + l * 256;
            int r = u >> 2, c = u & 3;
            cp_async16(bb + (uint32_t)(r * ROWB + c * 16),
                       Bh + (size_t)(col0 + r) * DDIM + kb + c * 8);
        }
        asm volatile("cp.async.commit_group;" ::: "memory");
    };

    #pragma unroll
    for (int p = 0; p < NSTAGE; p++) fill(p);

    const int lrow = lane & 15;          // row within 16
    const int lkb = (lane >> 4) * 16;    // khalf byte offset

    for (int i = 0; i < NITER; i++) {
        if (i < NITER - 3)      asm volatile("cp.async.wait_group 3;" ::: "memory");
        else if (i == NITER - 3) asm volatile("cp.async.wait_group 2;" ::: "memory");
        else if (i == NITER - 2) asm volatile("cp.async.wait_group 1;" ::: "memory");
        else                     asm volatile("cp.async.wait_group 0;" ::: "memory");
        __syncthreads();

        const uint32_t ab = sbase + (i & (NSTAGE - 1)) * STAGE_BYTES;
        const uint32_t bb = ab + A_BYTES;

        #pragma unroll
        for (int ks = 0; ks < 2; ks++) {
            const uint32_t koff = (uint32_t)(ks * 32 + lkb);
            uint32_t af[2][4];
            #pragma unroll
            for (int mt = 0; mt < 2; mt++)
                ldmatrix_x4(af[mt], ab + (uint32_t)((wm * 32 + mt * 16 + lrow) * ROWB) + koff);
            uint32_t bf[8][2];
            #pragma unroll
            for (int t = 0; t < 4; t++) {
                uint32_t r[4];
                ldmatrix_x4(r, bb + (uint32_t)((wn * 64 + t * 16 + lrow) * ROWB) + koff);
                bf[t * 2][0] = r[0]; bf[t * 2][1] = r[2];
                bf[t * 2 + 1][0] = r[1]; bf[t * 2 + 1][1] = r[3];
            }
            #pragma unroll
            for (int mt = 0; mt < 2; mt++)
                #pragma unroll
                for (int nt = 0; nt < 8; nt++)
                    mma_bf16(acc[mt][nt], af[mt], bf[nt]);
        }
        __syncthreads();
        if (i + NSTAGE < NITER) fill(i + NSTAGE);
    }

    // -------- epilogue --------
    const float var = g_var;
    const int qrow = lane >> 2;
    const int qcol = (lane & 3) * 2;

    #pragma unroll
    for (int mt = 0; mt < 2; mt++) {
        const int rg = row0 + wm * 32 + mt * 16 + qrow;
        const float rnA = n1[rg];
        const float rnB = n1[rg + 8];
        #pragma unroll
        for (int nt = 0; nt < 8; nt++) {
            const int cg = col0 + wn * 64 + nt * 8 + qcol;
            float2 nn = *(const float2*)(n2 + cg);
            float sq0 = fmaxf(fmaf(-2.0f, acc[mt][nt][0], rnA + nn.x), 0.0f);
            float sq1 = fmaxf(fmaf(-2.0f, acc[mt][nt][1], rnA + nn.y), 0.0f);
            float sq2 = fmaxf(fmaf(-2.0f, acc[mt][nt][2], rnB + nn.x), 0.0f);
            float sq3 = fmaxf(fmaf(-2.0f, acc[mt][nt][3], rnB + nn.y), 0.0f);
            float2 v0 = make_float2(var * __expf(-0.5f * sq0), var * __expf(-0.5f * sq1));
            float2 v1 = make_float2(var * __expf(-0.5f * sq2), var * __expf(-0.5f * sq3));
            *(float2*)(out + (size_t)rg * Mcols + cg) = v0;
            *(float2*)(out + (size_t)(rg + 8) * Mcols + cg) = v1;
        }
    }
}

// -------------------- launch --------------------
extern "C" void kernel_launch(void* const* d_in, const int* in_sizes, int n_in,
                              void* d_out, int out_size) {
    const float* x1 = (const float*)d_in[0];
    const float* x2 = (const float*)d_in[1];
    const float* alpha_raw = (const float*)d_in[2];
    const float* variance_raw = (const float*)d_in[3];
    float* out = (float*)d_out;

    int N = in_sizes[0] / DDIM;
    int M = in_sizes[1] / DDIM;

    __nv_bfloat16 *A2, *Bh;
    float *n1, *n2;
    cudaGetSymbolAddress((void**)&A2, g_A2);
    cudaGetSymbolAddress((void**)&Bh, g_Bh);
    cudaGetSymbolAddress((void**)&n1, g_n1);
    cudaGetSymbolAddress((void**)&n2, g_n2);

    cudaFuncSetAttribute(rbf_mma_kernel, cudaFuncAttributeMaxDynamicSharedMemorySize, SMEM_TOTAL);

    prep_alpha_kernel<<<1, DDIM>>>(alpha_raw, variance_raw);
    scale_split_kernel<<<N, DDIM>>>(x1, A2, n1);
    scale_hi_kernel<<<M, DDIM>>>(x2, Bh, n2);

    dim3 grid(M / BN, N / BM);
    rbf_mma_kernel<<<grid, 256, SMEM_TOTAL>>>(A2, Bh, n1, n2, out, M);
}

// round 4
// speedup vs baseline: 2.7229x; 1.0368x over previous
#include <cuda_runtime.h>
#include <cuda_bf16.h>
#include <math.h>
#include <stdint.h>

#define DDIM 256
#define NROWS 8192
#define K2 512                 // A-side split K (hi || lo)
#define BM 128
#define BN 128
#define BK 32                  // bf16 per k-chunk
#define NITER (K2 / BK)        // 16
#define NSTAGE 4
#define ROWB 80                // smem bytes per row: 64 data + 16 pad
#define A_BYTES (BM * ROWB)    // 10240
#define STAGE_BYTES (2 * A_BYTES)
#define SMEM_TOTAL (NSTAGE * STAGE_BYTES)   // 81920

// -------------------- scratch --------------------
__device__ __nv_bfloat16 g_A2[NROWS * K2];    // x1*sa: hi (k<256) | lo (k>=256)
__device__ __nv_bfloat16 g_Bh[NROWS * DDIM];  // x2*sa: hi only
__device__ float g_n1[NROWS];
__device__ float g_n2[NROWS];
__device__ float g_sa[DDIM];
__device__ float g_var;

// -------------------- helpers --------------------
__device__ __forceinline__ uint32_t smem_u32(const void* p) {
    uint32_t a;
    asm("{ .reg .u64 t; cvta.to.shared.u64 t, %1; cvt.u32.u64 %0, t; }" : "=r"(a) : "l"(p));
    return a;
}
__device__ __forceinline__ void cp_async16(uint32_t saddr, const void* g) {
    asm volatile("cp.async.cg.shared.global [%0], [%1], 16;" :: "r"(saddr), "l"(g));
}
__device__ __forceinline__ void ldmatrix_x4(uint32_t* r, uint32_t saddr) {
    asm volatile("ldmatrix.sync.aligned.m8n8.x4.shared.b16 {%0,%1,%2,%3}, [%4];"
                 : "=r"(r[0]), "=r"(r[1]), "=r"(r[2]), "=r"(r[3]) : "r"(saddr));
}
__device__ __forceinline__ void mma_bf16(float* c, const uint32_t* a, const uint32_t* b) {
    asm volatile(
        "mma.sync.aligned.m16n8k16.row.col.f32.bf16.bf16.f32 "
        "{%0,%1,%2,%3}, {%4,%5,%6,%7}, {%8,%9}, {%0,%1,%2,%3};"
        : "+f"(c[0]), "+f"(c[1]), "+f"(c[2]), "+f"(c[3])
        : "r"(a[0]), "r"(a[1]), "r"(a[2]), "r"(a[3]), "r"(b[0]), "r"(b[1]));
}

// -------------------- prep --------------------
__global__ void prep_alpha_kernel(const float* __restrict__ alpha_raw,
                                  const float* __restrict__ variance_raw) {
    __shared__ float sh[DDIM];
    int d = threadIdx.x;
    float t = alpha_raw[d] * alpha_raw[d];
    sh[d] = t;
    __syncthreads();
    #pragma unroll
    for (int s = 128; s > 0; s >>= 1) {
        if (d < s) sh[d] = fmaxf(sh[d], sh[d + s]);
        __syncthreads();
    }
    float mx = sh[0];
    __syncthreads();
    float e = expf(t - mx);
    sh[d] = e;
    __syncthreads();
    #pragma unroll
    for (int s = 128; s > 0; s >>= 1) {
        if (d < s) sh[d] += sh[d + s];
        __syncthreads();
    }
    g_sa[d] = sqrtf(e / sh[0]);
    if (d == 0) g_var = variance_raw[0] * variance_raw[0];
}

__global__ void scale_split_kernel(const float* __restrict__ x,
                                   __nv_bfloat16* __restrict__ out,
                                   float* __restrict__ nrm) {
    __shared__ float sh[DDIM];
    int row = blockIdx.x, d = threadIdx.x;
    float v = x[(size_t)row * DDIM + d] * g_sa[d];
    __nv_bfloat16 hi = __float2bfloat16(v);
    out[(size_t)row * K2 + d] = hi;
    out[(size_t)row * K2 + DDIM + d] = __float2bfloat16(v - __bfloat162float(hi));
    sh[d] = v * v;
    __syncthreads();
    #pragma unroll
    for (int s = 128; s > 0; s >>= 1) {
        if (d < s) sh[d] += sh[d + s];
        __syncthreads();
    }
    if (d == 0) nrm[row] = sh[0];
}

__global__ void scale_hi_kernel(const float* __restrict__ x,
                                __nv_bfloat16* __restrict__ out,
                                float* __restrict__ nrm) {
    __shared__ float sh[DDIM];
    int row = blockIdx.x, d = threadIdx.x;
    float v = x[(size_t)row * DDIM + d] * g_sa[d];
    out[(size_t)row * DDIM + d] = __float2bfloat16(v);
    sh[d] = v * v;
    __syncthreads();
    #pragma unroll
    for (int s = 128; s > 0; s >>= 1) {
        if (d < s) sh[d] += sh[d + s];
        __syncthreads();
    }
    if (d == 0) nrm[row] = sh[0];
}

// -------------------- fused HMMA GEMM + RBF epilogue --------------------
__global__ void __launch_bounds__(256, 2)
rbf_mma_kernel(const __nv_bfloat16* __restrict__ A2,
               const __nv_bfloat16* __restrict__ Bh,
               const float* __restrict__ n1,
               const float* __restrict__ n2,
               float* __restrict__ out,
               int Mcols) {
    extern __shared__ char smem[];
    const uint32_t sbase = smem_u32(smem);
    const int tid = threadIdx.x;
    const int wid = tid >> 5;
    const int lane = tid & 31;
    const int wm = wid & 3;       // 4 warps in M, 32 rows each
    const int wn = wid >> 2;      // 2 warps in N, 64 cols each
    const int row0 = blockIdx.y * BM;
    const int col0 = blockIdx.x * BN;

    float acc[2][8][4];
    #pragma unroll
    for (int i = 0; i < 2; i++)
        #pragma unroll
        for (int j = 0; j < 8; j++)
            #pragma unroll
            for (int q = 0; q < 4; q++) acc[i][j][q] = 0.0f;

    // ---- hoisted per-thread load state ----
    // A: 2 chunks/thread, B: 2 chunks/thread (each 16B)
    uint32_t aoff[2], boff[2];
    const __nv_bfloat16 *agp[2], *bgp[2];
    #pragma unroll
    for (int l = 0; l < 2; l++) {
        int u = tid + l * 256;
        int r = u >> 2, c = u & 3;
        aoff[l] = (uint32_t)(r * ROWB + c * 16);
        agp[l]  = A2 + (size_t)(row0 + r) * K2 + c * 8;
        boff[l] = (uint32_t)(r * ROWB + c * 16);
        bgp[l]  = Bh + (size_t)(col0 + r) * DDIM + c * 8;
    }

    auto fill = [&](int ck) {
        const int kk = ck * BK;
        const int kb = kk & (DDIM - 1);
        const uint32_t ab = sbase + (ck & (NSTAGE - 1)) * STAGE_BYTES;
        const uint32_t bb = ab + A_BYTES;
        #pragma unroll
        for (int l = 0; l < 2; l++)
            cp_async16(ab + aoff[l], agp[l] + kk);
        #pragma unroll
        for (int l = 0; l < 2; l++)
            cp_async16(bb + boff[l], bgp[l] + kb);
        asm volatile("cp.async.commit_group;" ::: "memory");
    };

    // ---- hoisted ldmatrix within-stage offsets ----
    const int lrow = lane & 15;
    const uint32_t lkb = (uint32_t)((lane >> 4) * 16);
    uint32_t afoff[2], bfoff[4];
    #pragma unroll
    for (int mt = 0; mt < 2; mt++)
        afoff[mt] = (uint32_t)((wm * 32 + mt * 16 + lrow) * ROWB) + lkb;
    #pragma unroll
    for (int t = 0; t < 4; t++)
        bfoff[t] = (uint32_t)((wn * 64 + t * 16 + lrow) * ROWB) + lkb + A_BYTES;

    // prologue: fill NSTAGE-1 = 3 stages
    fill(0); fill(1); fill(2);

    for (int i = 0; i < NITER; i++) {
        if (i < NITER - 2)      asm volatile("cp.async.wait_group 2;" ::: "memory");
        else if (i == NITER - 2) asm volatile("cp.async.wait_group 1;" ::: "memory");
        else                     asm volatile("cp.async.wait_group 0;" ::: "memory");
        __syncthreads();

        if (i + 3 < NITER) fill(i + 3);

        const uint32_t stb = sbase + (i & (NSTAGE - 1)) * STAGE_BYTES;

        #pragma unroll
        for (int ks = 0; ks < 2; ks++) {
            const uint32_t koff = stb + (uint32_t)(ks * 32);
            uint32_t af[2][4];
            #pragma unroll
            for (int mt = 0; mt < 2; mt++)
                ldmatrix_x4(af[mt], koff + afoff[mt]);
            uint32_t bf[8][2];
            #pragma unroll
            for (int t = 0; t < 4; t++) {
                uint32_t r[4];
                ldmatrix_x4(r, koff + bfoff[t]);
                bf[t * 2][0] = r[0]; bf[t * 2][1] = r[2];
                bf[t * 2 + 1][0] = r[1]; bf[t * 2 + 1][1] = r[3];
            }
            #pragma unroll
            for (int mt = 0; mt < 2; mt++)
                #pragma unroll
                for (int nt = 0; nt < 8; nt++)
                    mma_bf16(acc[mt][nt], af[mt], bf[nt]);
        }
    }

    // -------- epilogue --------
    const float var = g_var;
    const int qrow = lane >> 2;
    const int qcol = (lane & 3) * 2;

    #pragma unroll
    for (int mt = 0; mt < 2; mt++) {
        const int rg = row0 + wm * 32 + mt * 16 + qrow;
        const float rnA = n1[rg];
        const float rnB = n1[rg + 8];
        #pragma unroll
        for (int nt = 0; nt < 8; nt++) {
            const int cg = col0 + wn * 64 + nt * 8 + qcol;
            float2 nn = *(const float2*)(n2 + cg);
            float sq0 = fmaxf(fmaf(-2.0f, acc[mt][nt][0], rnA + nn.x), 0.0f);
            float sq1 = fmaxf(fmaf(-2.0f, acc[mt][nt][1], rnA + nn.y), 0.0f);
            float sq2 = fmaxf(fmaf(-2.0f, acc[mt][nt][2], rnB + nn.x), 0.0f);
            float sq3 = fmaxf(fmaf(-2.0f, acc[mt][nt][3], rnB + nn.y), 0.0f);
            float2 v0 = make_float2(var * __expf(-0.5f * sq0), var * __expf(-0.5f * sq1));
            float2 v1 = make_float2(var * __expf(-0.5f * sq2), var * __expf(-0.5f * sq3));
            *(float2*)(out + (size_t)rg * Mcols + cg) = v0;
            *(float2*)(out + (size_t)(rg + 8) * Mcols + cg) = v1;
        }
    }
}

// -------------------- launch --------------------
extern "C" void kernel_launch(void* const* d_in, const int* in_sizes, int n_in,
                              void* d_out, int out_size) {
    const float* x1 = (const float*)d_in[0];
    const float* x2 = (const float*)d_in[1];
    const float* alpha_raw = (const float*)d_in[2];
    const float* variance_raw = (const float*)d_in[3];
    float* out = (float*)d_out;

    int N = in_sizes[0] / DDIM;
    int M = in_sizes[1] / DDIM;

    __nv_bfloat16 *A2, *Bh;
    float *n1, *n2;
    cudaGetSymbolAddress((void**)&A2, g_A2);
    cudaGetSymbolAddress((void**)&Bh, g_Bh);
    cudaGetSymbolAddress((void**)&n1, g_n1);
    cudaGetSymbolAddress((void**)&n2, g_n2);

    cudaFuncSetAttribute(rbf_mma_kernel, cudaFuncAttributeMaxDynamicSharedMemorySize, SMEM_TOTAL);

    prep_alpha_kernel<<<1, DDIM>>>(alpha_raw, variance_raw);
    scale_split_kernel<<<N, DDIM>>>(x1, A2, n1);
    scale_hi_kernel<<<M, DDIM>>>(x2, Bh, n2);

    dim3 grid(M / BN, N / BM);
    rbf_mma_kernel<<<grid, 256, SMEM_TOTAL>>>(A2, Bh, n1, n2, out, M);
}

// round 5
// speedup vs baseline: 2.9082x; 1.0681x over previous
#include <cuda_runtime.h>
#include <cuda_bf16.h>
#include <math.h>
#include <stdint.h>

#define DDIM 256
#define NROWS 8192
#define K2 512                    // A-side split K (hi || lo)
#define BM 128
#define BN 128
#define BK 64                     // bf16 per k-chunk
#define NITER (K2 / BK)           // 8
#define NSTAGE 3
#define ROWB 144                  // 128B data + 16B pad (conflict-free ldmatrix)
#define A_BYTES (BM * ROWB)       // 18432
#define STAGE_BYTES ((BM + BN) * ROWB)   // 36864
#define SMEM_TOTAL (NSTAGE * STAGE_BYTES) // 110592 -> 2 CTAs/SM (221KB)

// -------------------- scratch --------------------
__device__ __nv_bfloat16 g_A2[NROWS * K2];    // x1*sa: hi (k<256) | lo (k>=256)
__device__ __nv_bfloat16 g_Bh[NROWS * DDIM];  // x2*sa: hi only
__device__ float g_n1[NROWS];
__device__ float g_n2[NROWS];

// -------------------- helpers --------------------
__device__ __forceinline__ uint32_t smem_u32(const void* p) {
    uint32_t a;
    asm("{ .reg .u64 t; cvta.to.shared.u64 t, %1; cvt.u32.u64 %0, t; }" : "=r"(a) : "l"(p));
    return a;
}
__device__ __forceinline__ void cp_async16(uint32_t saddr, const void* g) {
    asm volatile("cp.async.cg.shared.global [%0], [%1], 16;" :: "r"(saddr), "l"(g));
}
__device__ __forceinline__ void ldmatrix_x4(uint32_t* r, uint32_t saddr) {
    asm volatile("ldmatrix.sync.aligned.m8n8.x4.shared.b16 {%0,%1,%2,%3}, [%4];"
                 : "=r"(r[0]), "=r"(r[1]), "=r"(r[2]), "=r"(r[3]) : "r"(saddr));
}
__device__ __forceinline__ void mma_bf16(float* c, const uint32_t* a, const uint32_t* b) {
    asm volatile(
        "mma.sync.aligned.m16n8k16.row.col.f32.bf16.bf16.f32 "
        "{%0,%1,%2,%3}, {%4,%5,%6,%7}, {%8,%9}, {%0,%1,%2,%3};"
        : "+f"(c[0]), "+f"(c[1]), "+f"(c[2]), "+f"(c[3])
        : "r"(a[0]), "r"(a[1]), "r"(a[2]), "r"(a[3]), "r"(b[0]), "r"(b[1]));
}

// -------------------- fused prep: softmax(alpha^2) + scale/split + norms ----
// Blocks [0, N) handle x1 rows (hi|lo into A2, norm into n1).
// Blocks [N, N+M) handle x2 rows (hi into Bh, norm into n2).
// Each block recomputes sqrt(softmax) locally (256 exps, negligible).
__global__ void prep_kernel(const float* __restrict__ x1,
                            const float* __restrict__ x2,
                            const float* __restrict__ alpha_raw,
                            __nv_bfloat16* __restrict__ A2,
                            __nv_bfloat16* __restrict__ Bh,
                            float* __restrict__ n1,
                            float* __restrict__ n2,
                            int N) {
    __shared__ float sh[DDIM];
    const int d = threadIdx.x;

    float t = alpha_raw[d] * alpha_raw[d];
    sh[d] = t;
    __syncthreads();
    #pragma unroll
    for (int s = 128; s > 0; s >>= 1) {
        if (d < s) sh[d] = fmaxf(sh[d], sh[d + s]);
        __syncthreads();
    }
    float mx = sh[0];
    __syncthreads();
    float e = expf(t - mx);
    sh[d] = e;
    __syncthreads();
    #pragma unroll
    for (int s = 128; s > 0; s >>= 1) {
        if (d < s) sh[d] += sh[d + s];
        __syncthreads();
    }
    const float sa = sqrtf(e / sh[0]);
    __syncthreads();

    const int b = blockIdx.x;
    float v;
    if (b < N) {
        v = x1[(size_t)b * DDIM + d] * sa;
        __nv_bfloat16 hi = __float2bfloat16(v);
        A2[(size_t)b * K2 + d] = hi;
        A2[(size_t)b * K2 + DDIM + d] = __float2bfloat16(v - __bfloat162float(hi));
    } else {
        v = x2[(size_t)(b - N) * DDIM + d] * sa;
        Bh[(size_t)(b - N) * DDIM + d] = __float2bfloat16(v);
    }
    sh[d] = v * v;
    __syncthreads();
    #pragma unroll
    for (int s = 128; s > 0; s >>= 1) {
        if (d < s) sh[d] += sh[d + s];
        __syncthreads();
    }
    if (d == 0) {
        if (b < N) n1[b] = sh[0];
        else       n2[b - N] = sh[0];
    }
}

// -------------------- fused HMMA GEMM + RBF epilogue --------------------
__global__ void __launch_bounds__(256, 2)
rbf_mma_kernel(const __nv_bfloat16* __restrict__ A2,
               const __nv_bfloat16* __restrict__ Bh,
               const float* __restrict__ n1,
               const float* __restrict__ n2,
               const float* __restrict__ variance_raw,
               float* __restrict__ out,
               int Mcols) {
    extern __shared__ char smem[];
    const uint32_t sbase = smem_u32(smem);
    const int tid = threadIdx.x;
    const int wid = tid >> 5;
    const int lane = tid & 31;
    const int wm = wid & 3;       // 4 warps in M, 32 rows each
    const int wn = wid >> 2;      // 2 warps in N, 64 cols each
    const int row0 = blockIdx.y * BM;
    const int col0 = blockIdx.x * BN;

    float acc[2][8][4];
    #pragma unroll
    for (int i = 0; i < 2; i++)
        #pragma unroll
        for (int j = 0; j < 8; j++)
            #pragma unroll
            for (int q = 0; q < 4; q++) acc[i][j][q] = 0.0f;

    // ---- hoisted per-thread load state: 4 A-chunks + 4 B-chunks of 16B ----
    // 1024 chunks per matrix per stage, 256 threads -> 4 each.
    uint32_t coff[4];
    const __nv_bfloat16 *agp[4], *bgp[4];
    #pragma unroll
    for (int l = 0; l < 4; l++) {
        int u = tid + l * 256;
        int r = u >> 3, c = u & 7;         // r in [0,128), c in [0,8) (16B units)
        coff[l] = (uint32_t)(r * ROWB + c * 16);
        agp[l] = A2 + (size_t)(row0 + r) * K2 + c * 8;
        bgp[l] = Bh + (size_t)(col0 + r) * DDIM + c * 8;
    }

    auto fill = [&](int ck) {
        const int kk = ck * BK;
        const int kb = kk & (DDIM - 1);
        const uint32_t ab = sbase + (ck % NSTAGE) * STAGE_BYTES;
        const uint32_t bb = ab + A_BYTES;
        #pragma unroll
        for (int l = 0; l < 4; l++)
            cp_async16(ab + coff[l], agp[l] + kk);
        #pragma unroll
        for (int l = 0; l < 4; l++)
            cp_async16(bb + coff[l], bgp[l] + kb);
        asm volatile("cp.async.commit_group;" ::: "memory");
    };

    // ---- hoisted ldmatrix within-stage offsets ----
    const int lrow = lane & 15;
    const uint32_t lkb = (uint32_t)((lane >> 4) * 16);
    uint32_t afoff[2], bfoff[4];
    #pragma unroll
    for (int mt = 0; mt < 2; mt++)
        afoff[mt] = (uint32_t)((wm * 32 + mt * 16 + lrow) * ROWB) + lkb;
    #pragma unroll
    for (int t = 0; t < 4; t++)
        bfoff[t] = (uint32_t)((wn * 64 + t * 16 + lrow) * ROWB) + lkb + A_BYTES;

    // prologue: fill 2 stages
    fill(0); fill(1);

    #pragma unroll
    for (int i = 0; i < NITER; i++) {
        if (i < NITER - 1) asm volatile("cp.async.wait_group 1;" ::: "memory");
        else               asm volatile("cp.async.wait_group 0;" ::: "memory");
        __syncthreads();

        if (i + 2 < NITER) fill(i + 2);

        const uint32_t stb = sbase + (i % NSTAGE) * STAGE_BYTES;

        #pragma unroll
        for (int ks = 0; ks < 4; ks++) {
            const uint32_t koff = stb + (uint32_t)(ks * 32);
            uint32_t af[2][4];
            #pragma unroll
            for (int mt = 0; mt < 2; mt++)
                ldmatrix_x4(af[mt], koff + afoff[mt]);
            uint32_t bf[8][2];
            #pragma unroll
            for (int t = 0; t < 4; t++) {
                uint32_t r[4];
                ldmatrix_x4(r, koff + bfoff[t]);
                bf[t * 2][0] = r[0]; bf[t * 2][1] = r[2];
                bf[t * 2 + 1][0] = r[1]; bf[t * 2 + 1][1] = r[3];
            }
            #pragma unroll
            for (int mt = 0; mt < 2; mt++)
                #pragma unroll
                for (int nt = 0; nt < 8; nt++)
                    mma_bf16(acc[mt][nt], af[mt], bf[nt]);
        }
    }

    // -------- epilogue --------
    const float vr = variance_raw[0];
    const float var = vr * vr;
    const int qrow = lane >> 2;
    const int qcol = (lane & 3) * 2;

    #pragma unroll
    for (int mt = 0; mt < 2; mt++) {
        const int rg = row0 + wm * 32 + mt * 16 + qrow;
        const float rnA = n1[rg];
        const float rnB = n1[rg + 8];
        #pragma unroll
        for (int nt = 0; nt < 8; nt++) {
            const int cg = col0 + wn * 64 + nt * 8 + qcol;
            float2 nn = *(const float2*)(n2 + cg);
            float sq0 = fmaxf(fmaf(-2.0f, acc[mt][nt][0], rnA + nn.x), 0.0f);
            float sq1 = fmaxf(fmaf(-2.0f, acc[mt][nt][1], rnA + nn.y), 0.0f);
            float sq2 = fmaxf(fmaf(-2.0f, acc[mt][nt][2], rnB + nn.x), 0.0f);
            float sq3 = fmaxf(fmaf(-2.0f, acc[mt][nt][3], rnB + nn.y), 0.0f);
            float2 v0 = make_float2(var * __expf(-0.5f * sq0), var * __expf(-0.5f * sq1));
            float2 v1 = make_float2(var * __expf(-0.5f * sq2), var * __expf(-0.5f * sq3));
            *(float2*)(out + (size_t)rg * Mcols + cg) = v0;
            *(float2*)(out + (size_t)(rg + 8) * Mcols + cg) = v1;
        }
    }
}

// -------------------- launch --------------------
extern "C" void kernel_launch(void* const* d_in, const int* in_sizes, int n_in,
                              void* d_out, int out_size) {
    const float* x1 = (const float*)d_in[0];
    const float* x2 = (const float*)d_in[1];
    const float* alpha_raw = (const float*)d_in[2];
    const float* variance_raw = (const float*)d_in[3];
    float* out = (float*)d_out;

    int N = in_sizes[0] / DDIM;
    int M = in_sizes[1] / DDIM;

    __nv_bfloat16 *A2, *Bh;
    float *n1, *n2;
    cudaGetSymbolAddress((void**)&A2, g_A2);
    cudaGetSymbolAddress((void**)&Bh, g_Bh);
    cudaGetSymbolAddress((void**)&n1, g_n1);
    cudaGetSymbolAddress((void**)&n2, g_n2);

    cudaFuncSetAttribute(rbf_mma_kernel, cudaFuncAttributeMaxDynamicSharedMemorySize, SMEM_TOTAL);

    prep_kernel<<<N + M, DDIM>>>(x1, x2, alpha_raw, A2, Bh, n1, n2, N);

    dim3 grid(M / BN, N / BM);
    rbf_mma_kernel<<<grid, 256, SMEM_TOTAL>>>(A2, Bh, n1, n2, variance_raw, out, M);
}